// round 3
// baseline (speedup 1.0000x reference)
#include <cuda_runtime.h>

// 2-layer GCN via CSR counting-sort + atomic-free gather aggregation.
//   A = D^{-1/2}(Adj+I)D^{-1/2}
//   agg1: z[i]  = dinv[i]*x[i]  + sum_{c in N(i)} dinv[c]*x[c]
//   h    = relu(dinv[r]*(z@W1) + b1)
//   y2   = dinv*(h@W2)
//   agg2: out[i] = dinv[i]*( y2[i] + sum y2[c] ) + b2

#define N_NODES 50000
#define N_EDGES 800000
#define DIM_IN 64
#define DIM_HID 128
#define SCAN_T 1024

__device__ int   g_cnt[N_NODES];
__device__ int   g_rp [N_NODES + 1];
__device__ int   g_wr [N_NODES];
__device__ int   g_col[N_EDGES];
__device__ float g_dinv[N_NODES];
__device__ float g_z   [N_NODES * DIM_IN];
__device__ float g_h   [N_NODES * DIM_HID];
__device__ float g_y2  [N_NODES * DIM_IN];

// ---------------- CSR build ----------------
__global__ void k_zero_cnt(int n) {
    int i = blockIdx.x * blockDim.x + threadIdx.x;
    if (i < n) g_cnt[i] = 0;
}
__global__ void k_count(const int* __restrict__ dst, int e) {
    int i = blockIdx.x * blockDim.x + threadIdx.x;
    if (i < e) atomicAdd(&g_cnt[dst[i]], 1);
}
// single-block exclusive scan of g_cnt -> g_rp, g_wr
__global__ void k_scan(int n) {
    __shared__ int part[SCAN_T];
    int t = threadIdx.x;
    int chunk = (n + SCAN_T - 1) / SCAN_T;
    int lo = t * chunk, hi = min(lo + chunk, n);
    int s = 0;
    for (int i = lo; i < hi; i++) s += g_cnt[i];
    part[t] = s;
    __syncthreads();
    for (int off = 1; off < SCAN_T; off <<= 1) {
        int v = (t >= off) ? part[t - off] : 0;
        __syncthreads();
        part[t] += v;
        __syncthreads();
    }
    int pre = (t == 0) ? 0 : part[t - 1];
    for (int i = lo; i < hi; i++) {
        g_rp[i] = pre;
        g_wr[i] = pre;
        pre += g_cnt[i];
    }
    if (t == SCAN_T - 1) g_rp[n] = pre;
}
__global__ void k_dinv(int n) {
    int i = blockIdx.x * blockDim.x + threadIdx.x;
    if (i < n) g_dinv[i] = rsqrtf((float)g_cnt[i] + 1.0f);
}
__global__ void k_scatter(const int* __restrict__ src, const int* __restrict__ dst, int e) {
    int i = blockIdx.x * blockDim.x + threadIdx.x;
    if (i < e) {
        int pos = atomicAdd(&g_wr[dst[i]], 1);
        g_col[pos] = src[i];
    }
}

// ---------------- gather aggregation (atomic-free) ----------------
// block (16,16): 16 lanes x 16 nodes. lane = one float4 of the 64-dim row.
template <bool PRESCALE, bool FINISH>
__global__ void k_agg(const float* __restrict__ F, float* __restrict__ O,
                      const float* __restrict__ bias, int n) {
    int node = blockIdx.x * 16 + threadIdx.y;
    if (node >= n) return;
    int lane = threadIdx.x;
    const float4* F4 = reinterpret_cast<const float4*>(F);
    float di = g_dinv[node];
    float4 v = F4[node * 16 + lane];
    float4 acc;
    if (PRESCALE) { acc.x = di * v.x; acc.y = di * v.y; acc.z = di * v.z; acc.w = di * v.w; }
    else          { acc = v; }
    int j   = g_rp[node];
    int end = g_rp[node + 1];
    // 2-wide unrolled gather loop for MLP
    for (; j + 2 <= end; j += 2) {
        int c0 = __ldg(&g_col[j]);
        int c1 = __ldg(&g_col[j + 1]);
        float4 u0 = F4[c0 * 16 + lane];
        float4 u1 = F4[c1 * 16 + lane];
        if (PRESCALE) {
            float s0 = g_dinv[c0], s1 = g_dinv[c1];
            acc.x = fmaf(s0, u0.x, acc.x); acc.y = fmaf(s0, u0.y, acc.y);
            acc.z = fmaf(s0, u0.z, acc.z); acc.w = fmaf(s0, u0.w, acc.w);
            acc.x = fmaf(s1, u1.x, acc.x); acc.y = fmaf(s1, u1.y, acc.y);
            acc.z = fmaf(s1, u1.z, acc.z); acc.w = fmaf(s1, u1.w, acc.w);
        } else {
            acc.x += u0.x + u1.x; acc.y += u0.y + u1.y;
            acc.z += u0.z + u1.z; acc.w += u0.w + u1.w;
        }
    }
    if (j < end) {
        int c0 = __ldg(&g_col[j]);
        float4 u0 = F4[c0 * 16 + lane];
        if (PRESCALE) {
            float s0 = g_dinv[c0];
            acc.x = fmaf(s0, u0.x, acc.x); acc.y = fmaf(s0, u0.y, acc.y);
            acc.z = fmaf(s0, u0.z, acc.z); acc.w = fmaf(s0, u0.w, acc.w);
        } else {
            acc.x += u0.x; acc.y += u0.y; acc.z += u0.z; acc.w += u0.w;
        }
    }
    float4 o;
    if (FINISH) {
        float4 bb = reinterpret_cast<const float4*>(bias)[lane];
        o.x = fmaf(di, acc.x, bb.x);
        o.y = fmaf(di, acc.y, bb.y);
        o.z = fmaf(di, acc.z, bb.z);
        o.w = fmaf(di, acc.w, bb.w);
    } else {
        o = acc;
    }
    reinterpret_cast<float4*>(O)[node * 16 + lane] = o;
}

// ---------------- GEMM1: h = relu(b1 + dinv[r] * (z_row @ W1))  [n,64]x[64,128] ----------------
__global__ void k_gemm1(const float* __restrict__ Z, const float* __restrict__ W,
                        const float* __restrict__ b, float* __restrict__ H, int n) {
    __shared__ float Ws[64 * 128];
    int tid = threadIdx.y * 32 + threadIdx.x;
    {
        const float4* w4 = reinterpret_cast<const float4*>(W);
        float4* s4 = reinterpret_cast<float4*>(Ws);
        for (int i = tid; i < 64 * 128 / 4; i += 256) s4[i] = w4[i];
    }
    __syncthreads();
    int r = blockIdx.x * 8 + threadIdx.y;
    if (r >= n) return;
    int tx = threadIdx.x;
    const float4* a4 = reinterpret_cast<const float4*>(Z + (size_t)r * 64);
    const float4* ws4 = reinterpret_cast<const float4*>(Ws);
    float4 acc = {0.f, 0.f, 0.f, 0.f};
    #pragma unroll
    for (int k4 = 0; k4 < 16; k4++) {
        float4 av = a4[k4];
        float4 w;
        w = ws4[(4 * k4 + 0) * 32 + tx];
        acc.x = fmaf(av.x, w.x, acc.x); acc.y = fmaf(av.x, w.y, acc.y);
        acc.z = fmaf(av.x, w.z, acc.z); acc.w = fmaf(av.x, w.w, acc.w);
        w = ws4[(4 * k4 + 1) * 32 + tx];
        acc.x = fmaf(av.y, w.x, acc.x); acc.y = fmaf(av.y, w.y, acc.y);
        acc.z = fmaf(av.y, w.z, acc.z); acc.w = fmaf(av.y, w.w, acc.w);
        w = ws4[(4 * k4 + 2) * 32 + tx];
        acc.x = fmaf(av.z, w.x, acc.x); acc.y = fmaf(av.z, w.y, acc.y);
        acc.z = fmaf(av.z, w.z, acc.z); acc.w = fmaf(av.z, w.w, acc.w);
        w = ws4[(4 * k4 + 3) * 32 + tx];
        acc.x = fmaf(av.w, w.x, acc.x); acc.y = fmaf(av.w, w.y, acc.y);
        acc.z = fmaf(av.w, w.z, acc.z); acc.w = fmaf(av.w, w.w, acc.w);
    }
    float s = g_dinv[r];
    float4 bb = reinterpret_cast<const float4*>(b)[tx];
    float4 o;
    o.x = fmaxf(fmaf(s, acc.x, bb.x), 0.f);
    o.y = fmaxf(fmaf(s, acc.y, bb.y), 0.f);
    o.z = fmaxf(fmaf(s, acc.z, bb.z), 0.f);
    o.w = fmaxf(fmaf(s, acc.w, bb.w), 0.f);
    reinterpret_cast<float4*>(H + (size_t)r * 128)[tx] = o;
}

// ---------------- GEMM2: y2 = dinv[r] * (h_row @ W2)  [n,128]x[128,64] ----------------
__global__ void k_gemm2(const float* __restrict__ H, const float* __restrict__ W,
                        float* __restrict__ Y2, int n) {
    __shared__ float Ws[128 * 64];
    int tid = threadIdx.y * 16 + threadIdx.x;
    {
        const float4* w4 = reinterpret_cast<const float4*>(W);
        float4* s4 = reinterpret_cast<float4*>(Ws);
        for (int i = tid; i < 128 * 64 / 4; i += 256) s4[i] = w4[i];
    }
    __syncthreads();
    int r = blockIdx.x * 16 + threadIdx.y;
    if (r >= n) return;
    int tx = threadIdx.x;
    const float4* a4 = reinterpret_cast<const float4*>(H + (size_t)r * 128);
    const float4* ws4 = reinterpret_cast<const float4*>(Ws);
    float4 acc = {0.f, 0.f, 0.f, 0.f};
    #pragma unroll
    for (int k4 = 0; k4 < 32; k4++) {
        float4 av = a4[k4];
        float4 w;
        w = ws4[(4 * k4 + 0) * 16 + tx];
        acc.x = fmaf(av.x, w.x, acc.x); acc.y = fmaf(av.x, w.y, acc.y);
        acc.z = fmaf(av.x, w.z, acc.z); acc.w = fmaf(av.x, w.w, acc.w);
        w = ws4[(4 * k4 + 1) * 16 + tx];
        acc.x = fmaf(av.y, w.x, acc.x); acc.y = fmaf(av.y, w.y, acc.y);
        acc.z = fmaf(av.y, w.z, acc.z); acc.w = fmaf(av.y, w.w, acc.w);
        w = ws4[(4 * k4 + 2) * 16 + tx];
        acc.x = fmaf(av.z, w.x, acc.x); acc.y = fmaf(av.z, w.y, acc.y);
        acc.z = fmaf(av.z, w.z, acc.z); acc.w = fmaf(av.z, w.w, acc.w);
        w = ws4[(4 * k4 + 3) * 16 + tx];
        acc.x = fmaf(av.w, w.x, acc.x); acc.y = fmaf(av.w, w.y, acc.y);
        acc.z = fmaf(av.w, w.z, acc.z); acc.w = fmaf(av.w, w.w, acc.w);
    }
    float s = g_dinv[r];
    float4 o = {s * acc.x, s * acc.y, s * acc.z, s * acc.w};
    reinterpret_cast<float4*>(Y2 + (size_t)r * 64)[tx] = o;
}

extern "C" void kernel_launch(void* const* d_in, const int* in_sizes, int n_in,
                              void* d_out, int out_size) {
    const float* x  = (const float*)d_in[0];
    const int*   ei = (const int*)  d_in[1];
    const float* W1 = (const float*)d_in[2];
    const float* b1 = (const float*)d_in[3];
    const float* W2 = (const float*)d_in[4];
    const float* b2 = (const float*)d_in[5];
    float* out = (float*)d_out;

    int n = in_sizes[0] / DIM_IN;   // 50000
    int e = in_sizes[1] / 2;        // 800000
    const int* src = ei;
    const int* dst = ei + e;

    float *z, *h, *y2;
    cudaGetSymbolAddress((void**)&z,  g_z);
    cudaGetSymbolAddress((void**)&h,  g_h);
    cudaGetSymbolAddress((void**)&y2, g_y2);

    const int TB = 256;

    // CSR build (by dst) + dinv
    k_zero_cnt<<<(n + TB - 1) / TB, TB>>>(n);
    k_count   <<<(e + TB - 1) / TB, TB>>>(dst, e);
    k_scan    <<<1, SCAN_T>>>(n);
    k_dinv    <<<(n + TB - 1) / TB, TB>>>(n);
    k_scatter <<<(e + TB - 1) / TB, TB>>>(src, dst, e);

    // layer 1: z = dinv*x + sum(dinv*x over neighbors)
    k_agg<true, false><<<(n + 15) / 16, dim3(16, 16)>>>(x, z, nullptr, n);
    k_gemm1<<<(n + 7) / 8, dim3(32, 8)>>>(z, W1, b1, h, n);

    // layer 2
    k_gemm2<<<(n + 15) / 16, dim3(16, 16)>>>(h, W2, y2, n);
    k_agg<false, true><<<(n + 15) / 16, dim3(16, 16)>>>(y2, out, b2, n);
}

// round 4
// speedup vs baseline: 1.3689x; 1.3689x over previous
#include <cuda_runtime.h>

// 2-layer GCN, bucketed gather aggregation (atomic-free hot loops).
//   A = D^{-1/2}(Adj+I)D^{-1/2}
//   y   = dinv*x
//   z_i = y_i + sum_{c in N(i)} y_c
//   h   = relu(dinv[r]*(z@W1) + b1)
//   y2  = dinv*(h@W2)
//   out_i = dinv_i*(y2_i + sum y2_c) + b2

#define N_NODES 50000
#define DIM_IN 64
#define DIM_HID 128
#define CAP 128   // max in-degree bucket capacity (Poisson(16) => P(deg>127) ~ 0)

__device__ int   g_cnt[N_NODES];
__device__ int   g_bucket[N_NODES * CAP];
__device__ float g_dinv[N_NODES];
__device__ float g_y   [N_NODES * DIM_IN];
__device__ float g_z   [N_NODES * DIM_IN];
__device__ float g_h   [N_NODES * DIM_HID];
__device__ float g_y2  [N_NODES * DIM_IN];

// ---------------- build ----------------
__global__ void k_zero(int n) {
    int i = blockIdx.x * blockDim.x + threadIdx.x;
    if (i < n) g_cnt[i] = 0;
}
__global__ void k_place(const int* __restrict__ src, const int* __restrict__ dst, int e) {
    int i = blockIdx.x * blockDim.x + threadIdx.x;
    if (i < e) {
        int d = dst[i];
        int pos = atomicAdd(&g_cnt[d], 1);
        g_bucket[d * CAP + pos] = src[i];
    }
}

// ---------------- prescale: y = dinv*x ; also materialize dinv ----------------
__global__ void k_prescale(const float* __restrict__ x, float* __restrict__ y, int n) {
    int idx = blockIdx.x * blockDim.x + threadIdx.x;  // n*16
    if (idx >= n * 16) return;
    int i = idx >> 4;
    float d = rsqrtf((float)g_cnt[i] + 1.0f);
    if ((idx & 15) == 0) g_dinv[i] = d;
    float4 v = reinterpret_cast<const float4*>(x)[idx];
    float4 o = {d * v.x, d * v.y, d * v.z, d * v.w};
    reinterpret_cast<float4*>(y)[idx] = o;
}

// ---------------- gather aggregation ----------------
// block (16,32): 32 nodes/block, 16 lanes = one float4 each of the 64-dim row.
// 4-wide int4 column loads -> 4 independent gathers in flight.
template <bool FINISH>
__global__ void k_agg(const float* __restrict__ F, float* __restrict__ O,
                      const float* __restrict__ bias, int n) {
    int node = blockIdx.x * 32 + threadIdx.y;
    if (node >= n) return;
    int lane = threadIdx.x;
    const float4* F4 = reinterpret_cast<const float4*>(F);
    const int4* cols4 = reinterpret_cast<const int4*>(g_bucket + node * CAP);
    int cnt = g_cnt[node];

    float4 acc = F4[node * 16 + lane];  // self term
    int j = 0;
    for (; j + 4 <= cnt; j += 4) {
        int4 c = __ldg(&cols4[j >> 2]);
        float4 u0 = F4[c.x * 16 + lane];
        float4 u1 = F4[c.y * 16 + lane];
        float4 u2 = F4[c.z * 16 + lane];
        float4 u3 = F4[c.w * 16 + lane];
        acc.x += (u0.x + u1.x) + (u2.x + u3.x);
        acc.y += (u0.y + u1.y) + (u2.y + u3.y);
        acc.z += (u0.z + u1.z) + (u2.z + u3.z);
        acc.w += (u0.w + u1.w) + (u2.w + u3.w);
    }
    if (j < cnt) {
        int4 c = __ldg(&cols4[j >> 2]);  // bucket row padded to CAP, safe to overread
        int rem = cnt - j;
        float4 u0 = F4[c.x * 16 + lane];
        acc.x += u0.x; acc.y += u0.y; acc.z += u0.z; acc.w += u0.w;
        if (rem > 1) {
            float4 u1 = F4[c.y * 16 + lane];
            acc.x += u1.x; acc.y += u1.y; acc.z += u1.z; acc.w += u1.w;
        }
        if (rem > 2) {
            float4 u2 = F4[c.z * 16 + lane];
            acc.x += u2.x; acc.y += u2.y; acc.z += u2.z; acc.w += u2.w;
        }
    }
    float4 o;
    if (FINISH) {
        float di = g_dinv[node];
        float4 bb = reinterpret_cast<const float4*>(bias)[lane];
        o.x = fmaf(di, acc.x, bb.x);
        o.y = fmaf(di, acc.y, bb.y);
        o.z = fmaf(di, acc.z, bb.z);
        o.w = fmaf(di, acc.w, bb.w);
    } else {
        o = acc;
    }
    reinterpret_cast<float4*>(O)[node * 16 + lane] = o;
}

// ---------------- GEMM1: h = relu(b1 + dinv[r] * (z_row @ W1))  [n,64]x[64,128] ----------------
__global__ void k_gemm1(const float* __restrict__ Z, const float* __restrict__ W,
                        const float* __restrict__ b, float* __restrict__ H, int n) {
    __shared__ float Ws[64 * 128];
    int tid = threadIdx.y * 32 + threadIdx.x;
    {
        const float4* w4 = reinterpret_cast<const float4*>(W);
        float4* s4 = reinterpret_cast<float4*>(Ws);
        for (int i = tid; i < 64 * 128 / 4; i += 256) s4[i] = w4[i];
    }
    __syncthreads();
    int r = blockIdx.x * 8 + threadIdx.y;
    if (r >= n) return;
    int tx = threadIdx.x;
    const float4* a4 = reinterpret_cast<const float4*>(Z + (size_t)r * 64);
    const float4* ws4 = reinterpret_cast<const float4*>(Ws);
    float4 acc = {0.f, 0.f, 0.f, 0.f};
    #pragma unroll
    for (int k4 = 0; k4 < 16; k4++) {
        float4 av = a4[k4];
        float4 w;
        w = ws4[(4 * k4 + 0) * 32 + tx];
        acc.x = fmaf(av.x, w.x, acc.x); acc.y = fmaf(av.x, w.y, acc.y);
        acc.z = fmaf(av.x, w.z, acc.z); acc.w = fmaf(av.x, w.w, acc.w);
        w = ws4[(4 * k4 + 1) * 32 + tx];
        acc.x = fmaf(av.y, w.x, acc.x); acc.y = fmaf(av.y, w.y, acc.y);
        acc.z = fmaf(av.y, w.z, acc.z); acc.w = fmaf(av.y, w.w, acc.w);
        w = ws4[(4 * k4 + 2) * 32 + tx];
        acc.x = fmaf(av.z, w.x, acc.x); acc.y = fmaf(av.z, w.y, acc.y);
        acc.z = fmaf(av.z, w.z, acc.z); acc.w = fmaf(av.z, w.w, acc.w);
        w = ws4[(4 * k4 + 3) * 32 + tx];
        acc.x = fmaf(av.w, w.x, acc.x); acc.y = fmaf(av.w, w.y, acc.y);
        acc.z = fmaf(av.w, w.z, acc.z); acc.w = fmaf(av.w, w.w, acc.w);
    }
    float s = g_dinv[r];
    float4 bb = reinterpret_cast<const float4*>(b)[tx];
    float4 o;
    o.x = fmaxf(fmaf(s, acc.x, bb.x), 0.f);
    o.y = fmaxf(fmaf(s, acc.y, bb.y), 0.f);
    o.z = fmaxf(fmaf(s, acc.z, bb.z), 0.f);
    o.w = fmaxf(fmaf(s, acc.w, bb.w), 0.f);
    reinterpret_cast<float4*>(H + (size_t)r * 128)[tx] = o;
}

// ---------------- GEMM2: y2 = dinv[r] * (h_row @ W2)  [n,128]x[128,64] ----------------
__global__ void k_gemm2(const float* __restrict__ H, const float* __restrict__ W,
                        float* __restrict__ Y2, int n) {
    __shared__ float Ws[128 * 64];
    int tid = threadIdx.y * 16 + threadIdx.x;
    {
        const float4* w4 = reinterpret_cast<const float4*>(W);
        float4* s4 = reinterpret_cast<float4*>(Ws);
        for (int i = tid; i < 128 * 64 / 4; i += 256) s4[i] = w4[i];
    }
    __syncthreads();
    int r = blockIdx.x * 16 + threadIdx.y;
    if (r >= n) return;
    int tx = threadIdx.x;
    const float4* a4 = reinterpret_cast<const float4*>(H + (size_t)r * 128);
    const float4* ws4 = reinterpret_cast<const float4*>(Ws);
    float4 acc = {0.f, 0.f, 0.f, 0.f};
    #pragma unroll
    for (int k4 = 0; k4 < 32; k4++) {
        float4 av = a4[k4];
        float4 w;
        w = ws4[(4 * k4 + 0) * 16 + tx];
        acc.x = fmaf(av.x, w.x, acc.x); acc.y = fmaf(av.x, w.y, acc.y);
        acc.z = fmaf(av.x, w.z, acc.z); acc.w = fmaf(av.x, w.w, acc.w);
        w = ws4[(4 * k4 + 1) * 16 + tx];
        acc.x = fmaf(av.y, w.x, acc.x); acc.y = fmaf(av.y, w.y, acc.y);
        acc.z = fmaf(av.y, w.z, acc.z); acc.w = fmaf(av.y, w.w, acc.w);
        w = ws4[(4 * k4 + 2) * 16 + tx];
        acc.x = fmaf(av.z, w.x, acc.x); acc.y = fmaf(av.z, w.y, acc.y);
        acc.z = fmaf(av.z, w.z, acc.z); acc.w = fmaf(av.z, w.w, acc.w);
        w = ws4[(4 * k4 + 3) * 16 + tx];
        acc.x = fmaf(av.w, w.x, acc.x); acc.y = fmaf(av.w, w.y, acc.y);
        acc.z = fmaf(av.w, w.z, acc.z); acc.w = fmaf(av.w, w.w, acc.w);
    }
    float s = g_dinv[r];
    float4 o = {s * acc.x, s * acc.y, s * acc.z, s * acc.w};
    reinterpret_cast<float4*>(Y2 + (size_t)r * 64)[tx] = o;
}

extern "C" void kernel_launch(void* const* d_in, const int* in_sizes, int n_in,
                              void* d_out, int out_size) {
    const float* x  = (const float*)d_in[0];
    const int*   ei = (const int*)  d_in[1];
    const float* W1 = (const float*)d_in[2];
    const float* b1 = (const float*)d_in[3];
    const float* W2 = (const float*)d_in[4];
    const float* b2 = (const float*)d_in[5];
    float* out = (float*)d_out;

    int n = in_sizes[0] / DIM_IN;   // 50000
    int e = in_sizes[1] / 2;        // 800000
    const int* src = ei;
    const int* dst = ei + e;

    float *y, *z, *h, *y2;
    cudaGetSymbolAddress((void**)&y,  g_y);
    cudaGetSymbolAddress((void**)&z,  g_z);
    cudaGetSymbolAddress((void**)&h,  g_h);
    cudaGetSymbolAddress((void**)&y2, g_y2);

    const int TB = 256;

    // bucket build
    k_zero <<<(n + TB - 1) / TB, TB>>>(n);
    k_place<<<(e + TB - 1) / TB, TB>>>(src, dst, e);

    // layer 1
    k_prescale<<<(n * 16 + TB - 1) / TB, TB>>>(x, y, n);
    k_agg<false><<<(n + 31) / 32, dim3(16, 32)>>>(y, z, nullptr, n);
    k_gemm1<<<(n + 7) / 8, dim3(32, 8)>>>(z, W1, b1, h, n);

    // layer 2
    k_gemm2<<<(n + 15) / 16, dim3(16, 16)>>>(h, W2, y2, n);
    k_agg<true><<<(n + 31) / 32, dim3(16, 32)>>>(y2, out, b2, n);
}

// round 5
// speedup vs baseline: 2.0460x; 1.4947x over previous
#include <cuda_runtime.h>

// 2-layer GCN, bucketed gather aggregation + register-tiled GEMMs.
//   y   = dinv*x
//   z_i = y_i + sum_{c in N(i)} y_c
//   h   = relu(dinv[r]*(z@W1) + b1)
//   y2  = dinv*(h@W2)
//   out_i = dinv_i*(y2_i + sum y2_c) + b2

#define N_NODES 50000
#define DIM_IN 64
#define DIM_HID 128
#define CAP 128

__device__ int   g_cnt[N_NODES];
__device__ int   g_bucket[N_NODES * CAP];
__device__ float g_dinv[N_NODES];
__device__ float g_y   [N_NODES * DIM_IN];
__device__ float g_z   [N_NODES * DIM_IN];
__device__ float g_h   [N_NODES * DIM_HID];
__device__ float g_y2  [N_NODES * DIM_IN];

// ---------------- build ----------------
__global__ void k_zero(int n) {
    int i = blockIdx.x * blockDim.x + threadIdx.x;
    if (i < n) g_cnt[i] = 0;
}
__global__ void k_place(const int* __restrict__ src, const int* __restrict__ dst, int e) {
    int i = blockIdx.x * blockDim.x + threadIdx.x;
    if (i < e) {
        int d = dst[i];
        int pos = atomicAdd(&g_cnt[d], 1);
        g_bucket[d * CAP + pos] = src[i];
    }
}

// ---------------- prescale: y = dinv*x ; materialize dinv ----------------
__global__ void k_prescale(const float* __restrict__ x, float* __restrict__ y, int n) {
    int idx = blockIdx.x * blockDim.x + threadIdx.x;  // n*16
    if (idx >= n * 16) return;
    int i = idx >> 4;
    float d = rsqrtf((float)g_cnt[i] + 1.0f);
    if ((idx & 15) == 0) g_dinv[i] = d;
    float4 v = reinterpret_cast<const float4*>(x)[idx];
    float4 o = {d * v.x, d * v.y, d * v.z, d * v.w};
    reinterpret_cast<float4*>(y)[idx] = o;
}

// ---------------- gather aggregation (unchanged from R4) ----------------
template <bool FINISH>
__global__ void k_agg(const float* __restrict__ F, float* __restrict__ O,
                      const float* __restrict__ bias, int n) {
    int node = blockIdx.x * 32 + threadIdx.y;
    if (node >= n) return;
    int lane = threadIdx.x;
    const float4* F4 = reinterpret_cast<const float4*>(F);
    const int4* cols4 = reinterpret_cast<const int4*>(g_bucket + node * CAP);
    int cnt = g_cnt[node];

    float4 acc = F4[node * 16 + lane];  // self term
    int j = 0;
    for (; j + 4 <= cnt; j += 4) {
        int4 c = __ldg(&cols4[j >> 2]);
        float4 u0 = F4[c.x * 16 + lane];
        float4 u1 = F4[c.y * 16 + lane];
        float4 u2 = F4[c.z * 16 + lane];
        float4 u3 = F4[c.w * 16 + lane];
        acc.x += (u0.x + u1.x) + (u2.x + u3.x);
        acc.y += (u0.y + u1.y) + (u2.y + u3.y);
        acc.z += (u0.z + u1.z) + (u2.z + u3.z);
        acc.w += (u0.w + u1.w) + (u2.w + u3.w);
    }
    if (j < cnt) {
        int4 c = __ldg(&cols4[j >> 2]);
        int rem = cnt - j;
        float4 u0 = F4[c.x * 16 + lane];
        acc.x += u0.x; acc.y += u0.y; acc.z += u0.z; acc.w += u0.w;
        if (rem > 1) {
            float4 u1 = F4[c.y * 16 + lane];
            acc.x += u1.x; acc.y += u1.y; acc.z += u1.z; acc.w += u1.w;
        }
        if (rem > 2) {
            float4 u2 = F4[c.z * 16 + lane];
            acc.x += u2.x; acc.y += u2.y; acc.z += u2.z; acc.w += u2.w;
        }
    }
    float4 o;
    if (FINISH) {
        float di = g_dinv[node];
        float4 bb = reinterpret_cast<const float4*>(bias)[lane];
        o.x = fmaf(di, acc.x, bb.x);
        o.y = fmaf(di, acc.y, bb.y);
        o.z = fmaf(di, acc.z, bb.z);
        o.w = fmaf(di, acc.w, bb.w);
    } else {
        o = acc;
    }
    reinterpret_cast<float4*>(O)[node * 16 + lane] = o;
}

// ---------------- GEMM1: h = relu(b1 + dinv[r]*(z@W1))  [n,64]x[64,128] ----------------
// block (32,8): tx = 4-col group (128 cols), each thread computes 4 rows.
// Block covers 32 rows; each LDS.128 of W reused across 4 rows.
__global__ void k_gemm1(const float* __restrict__ Z, const float* __restrict__ W,
                        const float* __restrict__ b, float* __restrict__ H, int n) {
    __shared__ float Ws[64 * 128];
    int tid = threadIdx.y * 32 + threadIdx.x;
    {
        const float4* w4 = reinterpret_cast<const float4*>(W);
        float4* s4 = reinterpret_cast<float4*>(Ws);
        for (int i = tid; i < 64 * 128 / 4; i += 256) s4[i] = w4[i];
    }
    __syncthreads();
    int tx = threadIdx.x;
    int r0 = blockIdx.x * 32 + threadIdx.y * 4;
    int rr0 = min(r0 + 0, n - 1), rr1 = min(r0 + 1, n - 1);
    int rr2 = min(r0 + 2, n - 1), rr3 = min(r0 + 3, n - 1);
    const float4* A4 = reinterpret_cast<const float4*>(Z);
    const float4* ws4 = reinterpret_cast<const float4*>(Ws);
    float4 a0 = {0,0,0,0}, a1 = a0, a2 = a0, a3 = a0;
    #pragma unroll
    for (int k4 = 0; k4 < 16; k4++) {
        float4 v0 = A4[rr0 * 16 + k4];
        float4 v1 = A4[rr1 * 16 + k4];
        float4 v2 = A4[rr2 * 16 + k4];
        float4 v3 = A4[rr3 * 16 + k4];
        float4 w;
        w = ws4[(4 * k4 + 0) * 32 + tx];
        a0.x = fmaf(v0.x, w.x, a0.x); a0.y = fmaf(v0.x, w.y, a0.y); a0.z = fmaf(v0.x, w.z, a0.z); a0.w = fmaf(v0.x, w.w, a0.w);
        a1.x = fmaf(v1.x, w.x, a1.x); a1.y = fmaf(v1.x, w.y, a1.y); a1.z = fmaf(v1.x, w.z, a1.z); a1.w = fmaf(v1.x, w.w, a1.w);
        a2.x = fmaf(v2.x, w.x, a2.x); a2.y = fmaf(v2.x, w.y, a2.y); a2.z = fmaf(v2.x, w.z, a2.z); a2.w = fmaf(v2.x, w.w, a2.w);
        a3.x = fmaf(v3.x, w.x, a3.x); a3.y = fmaf(v3.x, w.y, a3.y); a3.z = fmaf(v3.x, w.z, a3.z); a3.w = fmaf(v3.x, w.w, a3.w);
        w = ws4[(4 * k4 + 1) * 32 + tx];
        a0.x = fmaf(v0.y, w.x, a0.x); a0.y = fmaf(v0.y, w.y, a0.y); a0.z = fmaf(v0.y, w.z, a0.z); a0.w = fmaf(v0.y, w.w, a0.w);
        a1.x = fmaf(v1.y, w.x, a1.x); a1.y = fmaf(v1.y, w.y, a1.y); a1.z = fmaf(v1.y, w.z, a1.z); a1.w = fmaf(v1.y, w.w, a1.w);
        a2.x = fmaf(v2.y, w.x, a2.x); a2.y = fmaf(v2.y, w.y, a2.y); a2.z = fmaf(v2.y, w.z, a2.z); a2.w = fmaf(v2.y, w.w, a2.w);
        a3.x = fmaf(v3.y, w.x, a3.x); a3.y = fmaf(v3.y, w.y, a3.y); a3.z = fmaf(v3.y, w.z, a3.z); a3.w = fmaf(v3.y, w.w, a3.w);
        w = ws4[(4 * k4 + 2) * 32 + tx];
        a0.x = fmaf(v0.z, w.x, a0.x); a0.y = fmaf(v0.z, w.y, a0.y); a0.z = fmaf(v0.z, w.z, a0.z); a0.w = fmaf(v0.z, w.w, a0.w);
        a1.x = fmaf(v1.z, w.x, a1.x); a1.y = fmaf(v1.z, w.y, a1.y); a1.z = fmaf(v1.z, w.z, a1.z); a1.w = fmaf(v1.z, w.w, a1.w);
        a2.x = fmaf(v2.z, w.x, a2.x); a2.y = fmaf(v2.z, w.y, a2.y); a2.z = fmaf(v2.z, w.z, a2.z); a2.w = fmaf(v2.z, w.w, a2.w);
        a3.x = fmaf(v3.z, w.x, a3.x); a3.y = fmaf(v3.z, w.y, a3.y); a3.z = fmaf(v3.z, w.z, a3.z); a3.w = fmaf(v3.z, w.w, a3.w);
        w = ws4[(4 * k4 + 3) * 32 + tx];
        a0.x = fmaf(v0.w, w.x, a0.x); a0.y = fmaf(v0.w, w.y, a0.y); a0.z = fmaf(v0.w, w.z, a0.z); a0.w = fmaf(v0.w, w.w, a0.w);
        a1.x = fmaf(v1.w, w.x, a1.x); a1.y = fmaf(v1.w, w.y, a1.y); a1.z = fmaf(v1.w, w.z, a1.z); a1.w = fmaf(v1.w, w.w, a1.w);
        a2.x = fmaf(v2.w, w.x, a2.x); a2.y = fmaf(v2.w, w.y, a2.y); a2.z = fmaf(v2.w, w.z, a2.z); a2.w = fmaf(v2.w, w.w, a2.w);
        a3.x = fmaf(v3.w, w.x, a3.x); a3.y = fmaf(v3.w, w.y, a3.y); a3.z = fmaf(v3.w, w.z, a3.z); a3.w = fmaf(v3.w, w.w, a3.w);
    }
    float4 bb = reinterpret_cast<const float4*>(b)[tx];
    float4* H4 = reinterpret_cast<float4*>(H);
    #define EMIT1(ACC, R)                                                        \
        if ((R) < n) {                                                           \
            float s = g_dinv[R];                                                 \
            float4 o;                                                            \
            o.x = fmaxf(fmaf(s, ACC.x, bb.x), 0.f);                              \
            o.y = fmaxf(fmaf(s, ACC.y, bb.y), 0.f);                              \
            o.z = fmaxf(fmaf(s, ACC.z, bb.z), 0.f);                              \
            o.w = fmaxf(fmaf(s, ACC.w, bb.w), 0.f);                              \
            H4[(size_t)(R) * 32 + tx] = o;                                       \
        }
    EMIT1(a0, r0 + 0) EMIT1(a1, r0 + 1) EMIT1(a2, r0 + 2) EMIT1(a3, r0 + 3)
    #undef EMIT1
}

// ---------------- GEMM2: y2 = dinv[r]*(h@W2)  [n,128]x[128,64] ----------------
// block (16,16): tx = 4-col group (64 cols), 4 rows/thread, block covers 64 rows.
__global__ void k_gemm2(const float* __restrict__ H, const float* __restrict__ W,
                        float* __restrict__ Y2, int n) {
    __shared__ float Ws[128 * 64];
    int tid = threadIdx.y * 16 + threadIdx.x;
    {
        const float4* w4 = reinterpret_cast<const float4*>(W);
        float4* s4 = reinterpret_cast<float4*>(Ws);
        for (int i = tid; i < 128 * 64 / 4; i += 256) s4[i] = w4[i];
    }
    __syncthreads();
    int tx = threadIdx.x;
    int r0 = blockIdx.x * 64 + threadIdx.y * 4;
    int rr0 = min(r0 + 0, n - 1), rr1 = min(r0 + 1, n - 1);
    int rr2 = min(r0 + 2, n - 1), rr3 = min(r0 + 3, n - 1);
    const float4* A4 = reinterpret_cast<const float4*>(H);
    const float4* ws4 = reinterpret_cast<const float4*>(Ws);
    float4 a0 = {0,0,0,0}, a1 = a0, a2 = a0, a3 = a0;
    #pragma unroll
    for (int k4 = 0; k4 < 32; k4++) {
        float4 v0 = A4[rr0 * 32 + k4];
        float4 v1 = A4[rr1 * 32 + k4];
        float4 v2 = A4[rr2 * 32 + k4];
        float4 v3 = A4[rr3 * 32 + k4];
        float4 w;
        w = ws4[(4 * k4 + 0) * 16 + tx];
        a0.x = fmaf(v0.x, w.x, a0.x); a0.y = fmaf(v0.x, w.y, a0.y); a0.z = fmaf(v0.x, w.z, a0.z); a0.w = fmaf(v0.x, w.w, a0.w);
        a1.x = fmaf(v1.x, w.x, a1.x); a1.y = fmaf(v1.x, w.y, a1.y); a1.z = fmaf(v1.x, w.z, a1.z); a1.w = fmaf(v1.x, w.w, a1.w);
        a2.x = fmaf(v2.x, w.x, a2.x); a2.y = fmaf(v2.x, w.y, a2.y); a2.z = fmaf(v2.x, w.z, a2.z); a2.w = fmaf(v2.x, w.w, a2.w);
        a3.x = fmaf(v3.x, w.x, a3.x); a3.y = fmaf(v3.x, w.y, a3.y); a3.z = fmaf(v3.x, w.z, a3.z); a3.w = fmaf(v3.x, w.w, a3.w);
        w = ws4[(4 * k4 + 1) * 16 + tx];
        a0.x = fmaf(v0.y, w.x, a0.x); a0.y = fmaf(v0.y, w.y, a0.y); a0.z = fmaf(v0.y, w.z, a0.z); a0.w = fmaf(v0.y, w.w, a0.w);
        a1.x = fmaf(v1.y, w.x, a1.x); a1.y = fmaf(v1.y, w.y, a1.y); a1.z = fmaf(v1.y, w.z, a1.z); a1.w = fmaf(v1.y, w.w, a1.w);
        a2.x = fmaf(v2.y, w.x, a2.x); a2.y = fmaf(v2.y, w.y, a2.y); a2.z = fmaf(v2.y, w.z, a2.z); a2.w = fmaf(v2.y, w.w, a2.w);
        a3.x = fmaf(v3.y, w.x, a3.x); a3.y = fmaf(v3.y, w.y, a3.y); a3.z = fmaf(v3.y, w.z, a3.z); a3.w = fmaf(v3.y, w.w, a3.w);
        w = ws4[(4 * k4 + 2) * 16 + tx];
        a0.x = fmaf(v0.z, w.x, a0.x); a0.y = fmaf(v0.z, w.y, a0.y); a0.z = fmaf(v0.z, w.z, a0.z); a0.w = fmaf(v0.z, w.w, a0.w);
        a1.x = fmaf(v1.z, w.x, a1.x); a1.y = fmaf(v1.z, w.y, a1.y); a1.z = fmaf(v1.z, w.z, a1.z); a1.w = fmaf(v1.z, w.w, a1.w);
        a2.x = fmaf(v2.z, w.x, a2.x); a2.y = fmaf(v2.z, w.y, a2.y); a2.z = fmaf(v2.z, w.z, a2.z); a2.w = fmaf(v2.z, w.w, a2.w);
        a3.x = fmaf(v3.z, w.x, a3.x); a3.y = fmaf(v3.z, w.y, a3.y); a3.z = fmaf(v3.z, w.z, a3.z); a3.w = fmaf(v3.z, w.w, a3.w);
        w = ws4[(4 * k4 + 3) * 16 + tx];
        a0.x = fmaf(v0.w, w.x, a0.x); a0.y = fmaf(v0.w, w.y, a0.y); a0.z = fmaf(v0.w, w.z, a0.z); a0.w = fmaf(v0.w, w.w, a0.w);
        a1.x = fmaf(v1.w, w.x, a1.x); a1.y = fmaf(v1.w, w.y, a1.y); a1.z = fmaf(v1.w, w.z, a1.z); a1.w = fmaf(v1.w, w.w, a1.w);
        a2.x = fmaf(v2.w, w.x, a2.x); a2.y = fmaf(v2.w, w.y, a2.y); a2.z = fmaf(v2.w, w.z, a2.z); a2.w = fmaf(v2.w, w.w, a2.w);
        a3.x = fmaf(v3.w, w.x, a3.x); a3.y = fmaf(v3.w, w.y, a3.y); a3.z = fmaf(v3.w, w.z, a3.z); a3.w = fmaf(v3.w, w.w, a3.w);
    }
    float4* Y4 = reinterpret_cast<float4*>(Y2);
    #define EMIT2(ACC, R)                                                        \
        if ((R) < n) {                                                           \
            float s = g_dinv[R];                                                 \
            float4 o = {s * ACC.x, s * ACC.y, s * ACC.z, s * ACC.w};             \
            Y4[(size_t)(R) * 16 + tx] = o;                                       \
        }
    EMIT2(a0, r0 + 0) EMIT2(a1, r0 + 1) EMIT2(a2, r0 + 2) EMIT2(a3, r0 + 3)
    #undef EMIT2
}

extern "C" void kernel_launch(void* const* d_in, const int* in_sizes, int n_in,
                              void* d_out, int out_size) {
    const float* x  = (const float*)d_in[0];
    const int*   ei = (const int*)  d_in[1];
    const float* W1 = (const float*)d_in[2];
    const float* b1 = (const float*)d_in[3];
    const float* W2 = (const float*)d_in[4];
    const float* b2 = (const float*)d_in[5];
    float* out = (float*)d_out;

    int n = in_sizes[0] / DIM_IN;   // 50000
    int e = in_sizes[1] / 2;        // 800000
    const int* src = ei;
    const int* dst = ei + e;

    float *y, *z, *h, *y2;
    cudaGetSymbolAddress((void**)&y,  g_y);
    cudaGetSymbolAddress((void**)&z,  g_z);
    cudaGetSymbolAddress((void**)&h,  g_h);
    cudaGetSymbolAddress((void**)&y2, g_y2);

    const int TB = 256;

    // bucket build
    k_zero <<<(n + TB - 1) / TB, TB>>>(n);
    k_place<<<(e + TB - 1) / TB, TB>>>(src, dst, e);

    // layer 1
    k_prescale<<<(n * 16 + TB - 1) / TB, TB>>>(x, y, n);
    k_agg<false><<<(n + 31) / 32, dim3(16, 32)>>>(y, z, nullptr, n);
    k_gemm1<<<(n + 31) / 32, dim3(32, 8)>>>(z, W1, b1, h, n);

    // layer 2
    k_gemm2<<<(n + 63) / 64, dim3(16, 16)>>>(h, W2, y2, n);
    k_agg<true><<<(n + 31) / 32, dim3(16, 32)>>>(y2, out, b2, n);
}